// round 15
// baseline (speedup 1.0000x reference)
#include <cuda_runtime.h>
#include <cuda_bf16.h>
#include <cstdint>
#include <cstddef>

// Problem constants
#define C_ 4
#define B_ 64
#define T_ 512
#define D_ 256
#define U_ 512
#define OSC_ 5

typedef unsigned int u32;

// ---------------------------------------------------------------------------
// Helpers
// ---------------------------------------------------------------------------
__device__ __forceinline__ u32 prmt(u32 a, u32 b, u32 s) {
    u32 d;
    asm("prmt.b32 %0, %1, %2, %3;" : "=r"(d) : "r"(a), "r"(b), "r"(s));
    return d;
}

__device__ __forceinline__ u32 pack_bf(__nv_bfloat16 a, __nv_bfloat16 b) {
    return ((u32)__bfloat16_as_ushort(b) << 16) | (u32)__bfloat16_as_ushort(a);
}

__device__ __forceinline__ void split_bf(float v, __nv_bfloat16& hi, __nv_bfloat16& lo) {
    hi = __float2bfloat16(v);
    lo = __float2bfloat16(v - __bfloat162float(hi));
}

__device__ __forceinline__ void mma16816(float d[4], u32 a0, u32 a1, u32 a2, u32 a3,
                                         u32 b0, u32 b1) {
    asm("mma.sync.aligned.m16n8k16.row.col.f32.bf16.bf16.f32 "
        "{%0,%1,%2,%3}, {%4,%5,%6,%7}, {%8,%9}, {%0,%1,%2,%3};"
        : "+f"(d[0]), "+f"(d[1]), "+f"(d[2]), "+f"(d[3])
        : "r"(a0), "r"(a1), "r"(a2), "r"(a3), "r"(b0), "r"(b1));
}

// fragment permutation of h k-layout: within each 16-k block, thread tg's
// four k values {2tg, 2tg+1, 2tg+8, 2tg+9} become contiguous at [4tg..4tg+3]
__device__ __forceinline__ int permu(int u) {
    int r = u & 15;
    int t4 = (r & 7) >> 1;
    int slot = ((r >> 3) << 1) | (r & 1);
    return (u & ~15) | (t4 << 2) | slot;
}

__device__ __forceinline__ u32 s2u(const void* p) {
    u32 a;
    asm("{ .reg .u64 t; cvta.to.shared.u64 t, %1; cvt.u32.u64 %0, t; }"
        : "=r"(a) : "l"(p));
    return a;
}

// ---------------------------------------------------------------------------
// Scratch (device globals — no allocation allowed)
// ---------------------------------------------------------------------------
__device__ float g_xproj[8ull * T_ * B_ * U_];
__device__ float g_seq[(size_t)C_ * T_ * B_ * U_];
// double-buffered packed h (permu + bank-swizzled layout): lo16=hi, hi16=lo
__device__ u32 g_hsplit[2ull * C_ * B_ * U_];

// per-(cell,bgroup) barrier state: 8 domains of 16 blocks
__device__ unsigned g_bar_count[8] = {0};
__device__ unsigned g_bar_gen[8]   = {0};

// ---------------------------------------------------------------------------
// Phase 1: input projection GEMM via bf16 hi/lo split mma (verified R9-R14)
// ---------------------------------------------------------------------------
#define PJ_XPAD 40
#define PJ_WPAD 40

__global__ __launch_bounds__(256) void proj_mma_kernel(
    const float* __restrict__ x,
    const float* __restrict__ Wjx, const float* __restrict__ bjx,
    const float* __restrict__ Wkx, const float* __restrict__ bkx)
{
    __shared__ __nv_bfloat16 xs_hi[128 * PJ_XPAD];
    __shared__ __nv_bfloat16 xs_lo[128 * PJ_XPAD];
    __shared__ __nv_bfloat16 ws_hi[64 * PJ_WPAD];
    __shared__ __nv_bfloat16 ws_lo[64 * PJ_WPAD];

    const int zi = blockIdx.z;
    const int c  = zi >> 1;
    const int gt = zi & 1;
    const float* W  = (gt ? Wkx : Wjx) + (size_t)c * D_ * U_;
    const float* bi = (gt ? bkx : bjx) + (size_t)c * U_;

    const int m0 = blockIdx.x * 128;
    const int n0 = blockIdx.y * 64;
    const int tid = threadIdx.x;
    const int w   = tid >> 5;
    const int l   = tid & 31;
    const int g   = l >> 2;
    const int tg  = l & 3;
    const int wm  = w & 1;
    const int wn  = w >> 1;

    float2 bias2[2];
#pragma unroll
    for (int ni = 0; ni < 2; ni++)
        bias2[ni] = *(const float2*)&bi[n0 + wn * 16 + ni * 8 + tg * 2];

    float D[4][2][4];
#pragma unroll
    for (int mi = 0; mi < 4; mi++)
#pragma unroll
        for (int ni = 0; ni < 2; ni++)
#pragma unroll
            for (int q = 0; q < 4; q++) D[mi][ni][q] = 0.f;

    const int xr   = tid >> 1;
    const int half = tid & 1;
    const int wkr  = tid >> 3;
    const int wnc  = (tid & 7) * 8;

    for (int kc = 0; kc < 8; kc++) {
        __syncthreads();
        const float* xp = &x[(size_t)(m0 + xr) * D_ + kc * 32 + half * 16];
#pragma unroll
        for (int q = 0; q < 4; q++) {
            float4 v = *(const float4*)&xp[q * 4];
            __nv_bfloat16 h0, l0, h1, l1, h2, l2, h3, l3;
            split_bf(v.x, h0, l0); split_bf(v.y, h1, l1);
            split_bf(v.z, h2, l2); split_bf(v.w, h3, l3);
            int e = xr * PJ_XPAD + half * 16 + q * 4;
            *(u32*)&xs_hi[e]     = pack_bf(h0, h1);
            *(u32*)&xs_hi[e + 2] = pack_bf(h2, h3);
            *(u32*)&xs_lo[e]     = pack_bf(l0, l1);
            *(u32*)&xs_lo[e + 2] = pack_bf(l2, l3);
        }
        const float* wp = &W[(size_t)(kc * 32 + wkr) * U_ + n0 + wnc];
        float4 w0 = *(const float4*)wp;
        float4 w1 = *(const float4*)(wp + 4);
        float wv[8] = {w0.x, w0.y, w0.z, w0.w, w1.x, w1.y, w1.z, w1.w};
#pragma unroll
        for (int j = 0; j < 8; j++) {
            __nv_bfloat16 hh, ll;
            split_bf(wv[j], hh, ll);
            ws_hi[(wnc + j) * PJ_WPAD + wkr] = hh;
            ws_lo[(wnc + j) * PJ_WPAD + wkr] = ll;
        }
        __syncthreads();

        u32 Bh[2][2][2], Bl[2][2][2];
#pragma unroll
        for (int ni = 0; ni < 2; ni++)
#pragma unroll
            for (int ki = 0; ki < 2; ki++) {
                int e = (wn * 16 + ni * 8 + g) * PJ_WPAD + ki * 16 + tg * 2;
                Bh[ni][ki][0] = *(const u32*)&ws_hi[e];
                Bh[ni][ki][1] = *(const u32*)&ws_hi[e + 8];
                Bl[ni][ki][0] = *(const u32*)&ws_lo[e];
                Bl[ni][ki][1] = *(const u32*)&ws_lo[e + 8];
            }

#pragma unroll
        for (int mi = 0; mi < 4; mi++)
#pragma unroll
            for (int ki = 0; ki < 2; ki++) {
                int rb = (wm * 64 + mi * 16 + g) * PJ_XPAD + ki * 16 + tg * 2;
                u32 ah0 = *(const u32*)&xs_hi[rb];
                u32 ah1 = *(const u32*)&xs_hi[rb + 8 * PJ_XPAD];
                u32 ah2 = *(const u32*)&xs_hi[rb + 8];
                u32 ah3 = *(const u32*)&xs_hi[rb + 8 * PJ_XPAD + 8];
                u32 al0 = *(const u32*)&xs_lo[rb];
                u32 al1 = *(const u32*)&xs_lo[rb + 8 * PJ_XPAD];
                u32 al2 = *(const u32*)&xs_lo[rb + 8];
                u32 al3 = *(const u32*)&xs_lo[rb + 8 * PJ_XPAD + 8];
#pragma unroll
                for (int ni = 0; ni < 2; ni++) {
                    mma16816(D[mi][ni], ah0, ah1, ah2, ah3, Bh[ni][ki][0], Bh[ni][ki][1]);
                    mma16816(D[mi][ni], ah0, ah1, ah2, ah3, Bl[ni][ki][0], Bl[ni][ki][1]);
                    mma16816(D[mi][ni], al0, al1, al2, al3, Bh[ni][ki][0], Bh[ni][ki][1]);
                }
            }
    }

#pragma unroll
    for (int mi = 0; mi < 4; mi++)
#pragma unroll
        for (int ni = 0; ni < 2; ni++) {
            int col = n0 + wn * 16 + ni * 8 + tg * 2;
#pragma unroll
            for (int h = 0; h < 2; h++) {
                int m  = m0 + wm * 64 + mi * 16 + g + h * 8;
                int bb = m >> 9;
                int tt = m & 511;
                size_t off = ((size_t)(zi * T_ + tt) * B_ + bb) * U_ + col;
                float2 o;
                o.x = D[mi][ni][2 * h + 0] + bias2[ni].x;
                o.y = D[mi][ni][2 * h + 1] + bias2[ni].y;
                *(float2*)&g_xproj[off] = o;
            }
        }
}

// ---------------------------------------------------------------------------
// Phase 2: persistent scan — 128 CTAs x 128 threads, warp = k-quarter, both
//   m-halves per warp. h arrives per step via one 64 KB plain-bulk TMA into
//   smem (permu + XOR-swizzled layout, conflict-free LDS.128). Weights in a
//   phase-contiguous uint4 fragment layout. Software domain barrier (8 x 16).
// ---------------------------------------------------------------------------
#define NBG  2
#define BPG  32
#define NUC  16
#define UC   32
#define SC_NTH 128
#define PSTRIDE 66
#define WS_BYTES 131072                  // 8192 uint4 weight fragments
#define HS_OFF   WS_BYTES
#define HS_BYTES 65536                   // 32 rows x 512 u32
#define PART_OFF (WS_BYTES + HS_BYTES)
#define PART_FLOATS (4 * BPG * PSTRIDE)  // 8448
#define SC_SMEM_BYTES (PART_OFF + PART_FLOATS * 4)   // 230400
#define SC_DOM_BLKS 16

__global__ __launch_bounds__(SC_NTH, 1) void scan_kernel(
    const float* __restrict__ h0,
    const float* __restrict__ Wjh, const float* __restrict__ bjh,
    const float* __restrict__ Wkh, const float* __restrict__ bkh)
{
    extern __shared__ char smraw[];
    uint4* ws4  = (uint4*)smraw;                     // weight fragments
    u32*   hsm  = (u32*)(smraw + HS_OFF);            // [32][512] swizzled h
    float* part = (float*)(smraw + PART_OFF);        // [4 ks][32 b][PSTRIDE]
    __shared__ __align__(8) unsigned long long mbar;

    const int blk = blockIdx.x;          // c*32 + bg*16 + nc
    const int c   = blk >> 5;
    const int bg  = (blk >> 4) & 1;
    const int nc  = blk & 15;
    const int dom = c * 2 + bg;
    const int tid = threadIdx.x;
    const int ks  = tid >> 5;            // k-quarter 0..3
    const int l   = tid & 31;
    const int g   = l >> 2;
    const int tg  = l & 3;
    const int pu  = tid & 31;            // combine: u offset
    const int pbq = tid >> 5;            // combine: base batch (0..3)

    // ---- one-time: weights -> smem uint4 fragments (bh0,bh1,bl0,bl1) ----
    // entry e = ni*1024 + g2*256 + blk16*8 + glo*4 + tg  (phase-contiguous)
    for (int e = tid; e < 8192; e += SC_NTH) {
        int tg_ = e & 3, glo = (e >> 2) & 1, bk = (e >> 3) & 31;
        int g2 = (e >> 8) & 3, ni = (e >> 10) & 7;
        int col = ni * 8 + g2 * 2 + glo;
        int gate = col >> 5, uu = col & 31;
        const float* Wc = (gate ? Wkh : Wjh) + (size_t)c * U_ * U_;
        int ucol = nc * UC + uu;
        int k0 = bk * 16 + 2 * tg_;
        float wa = Wc[(size_t)(k0 + 0) * U_ + ucol];
        float wb = Wc[(size_t)(k0 + 1) * U_ + ucol];
        float wc2 = Wc[(size_t)(k0 + 8) * U_ + ucol];
        float wd = Wc[(size_t)(k0 + 9) * U_ + ucol];
        __nv_bfloat16 ha, la, hb, lb, hc, lc, hd, ld_;
        split_bf(wa, ha, la); split_bf(wb, hb, lb);
        split_bf(wc2, hc, lc); split_bf(wd, hd, ld_);
        ws4[e] = make_uint4(pack_bf(ha, hb), pack_bf(hc, hd),
                            pack_bf(la, lb), pack_bf(lc, ld_));
    }

    const u32 mb32  = s2u(&mbar);
    const u32 hsm32 = s2u(hsm);
    if (tid == 0)
        asm volatile("mbarrier.init.shared.b64 [%0], %1;"
                     :: "r"(mb32), "r"(1u) : "memory");

    const float bj_r = bjh[c * U_ + nc * UC + pu];
    const float bk_r = bkh[c * U_ + nc * UC + pu];
    const int pcol = permu(nc * UC + pu);
    // bank swizzle baked into global layout: chunk ^= (b&1)<<2
    const int wcol = ((((pcol >> 2) ^ ((pbq & 1) << 2)) << 2) | (pcol & 3));

    // ---- pack h0 slice into buffer 0; h_prev in regs ----
    float hprev[8];
    {
        u32* buf0 = g_hsplit + (size_t)c * B_ * U_;
#pragma unroll
        for (int r = 0; r < 8; r++) {
            int b = bg * BPG + pbq + r * 4;
            float hv = h0[(size_t)c * B_ * U_ + (size_t)b * U_ + nc * UC + pu];
            hprev[r] = hv;
            __nv_bfloat16 nh, nl;
            split_bf(hv, nh, nl);
            buf0[(size_t)b * U_ + wcol] =
                ((u32)__bfloat16_as_ushort(nl) << 16) | (u32)__bfloat16_as_ushort(nh);
        }
    }

    // ---- prefetch x projections for t = 0 ----
    float xjr[8], xkr[8];
    {
        const float* xj = g_xproj + ((size_t)(c * 2 + 0) * T_) * B_ * U_
                          + (size_t)(bg * BPG) * U_ + nc * UC + pu;
        const float* xk = g_xproj + ((size_t)(c * 2 + 1) * T_) * B_ * U_
                          + (size_t)(bg * BPG) * U_ + nc * UC + pu;
#pragma unroll
        for (int r = 0; r < 8; r++) {
            xjr[r] = __ldcs(&xj[(size_t)(pbq + r * 4) * U_]);
            xkr[r] = __ldcs(&xk[(size_t)(pbq + r * 4) * U_]);
        }
    }

    // ---- pre-loop domain barrier (publish h0 pack + mbar init) ----
    __threadfence();
    __syncthreads();
    if (tid == 0) {
        unsigned gen0, old;
        asm volatile("ld.acquire.gpu.u32 %0, [%1];"
                     : "=r"(gen0) : "l"(&g_bar_gen[dom]) : "memory");
        asm volatile("atom.acq_rel.gpu.add.u32 %0, [%1], 1;"
                     : "=r"(old) : "l"(&g_bar_count[dom]) : "memory");
        if (old == SC_DOM_BLKS - 1) {
            *(volatile unsigned*)&g_bar_count[dom] = 0;
            asm volatile("red.release.gpu.add.u32 [%0], 1;"
                         :: "l"(&g_bar_gen[dom]) : "memory");
        } else {
            unsigned gg;
            do {
                __nanosleep(20);
                asm volatile("ld.acquire.gpu.u32 %0, [%1];"
                             : "=r"(gg) : "l"(&g_bar_gen[dom]) : "memory");
            } while (gg == gen0);
        }
    }
    __syncthreads();

    const int sw = (g & 1) << 2;

    for (int t = 0; t < T_; t++) {
        // ---- TMA: pull this CTA's 64 KB h slice into smem ----
        if (tid == 0) {
            const u32* src = g_hsplit
                + ((size_t)(t & 1) * C_ + c) * B_ * U_ + (size_t)(bg * BPG) * U_;
            asm volatile("fence.proxy.async;" ::: "memory");
            asm volatile("mbarrier.arrive.expect_tx.shared.b64 _, [%0], %1;"
                         :: "r"(mb32), "r"(65536u) : "memory");
            asm volatile(
                "cp.async.bulk.shared::cluster.global.mbarrier::complete_tx::bytes "
                "[%0], [%1], %2, [%3];"
                :: "r"(hsm32), "l"(src), "r"(65536u), "r"(mb32) : "memory");
        }
        // wait (parity = t&1)
        {
            u32 ph = (u32)(t & 1);
            u32 done;
            asm volatile("{\n\t.reg .pred p;\n\t"
                "mbarrier.try_wait.parity.acquire.cta.shared::cta.b64 p, [%1], %2;\n\t"
                "selp.b32 %0, 1, 0, p;\n\t}"
                : "=r"(done) : "r"(mb32), "r"(ph) : "memory");
            while (!done) {
                asm volatile("{\n\t.reg .pred p;\n\t"
                    "mbarrier.try_wait.parity.acquire.cta.shared::cta.b64 p, [%1], %2, 0x989680;\n\t"
                    "selp.b32 %0, 1, 0, p;\n\t}"
                    : "=r"(done) : "r"(mb32), "r"(ph) : "memory");
            }
        }

        // ---- mma: both m-halves, this warp's 128-k quarter ----
        float D[2][8][4];
#pragma unroll
        for (int mt = 0; mt < 2; mt++)
#pragma unroll
            for (int ni = 0; ni < 8; ni++)
#pragma unroll
                for (int q = 0; q < 4; q++) D[mt][ni][q] = 0.f;

#pragma unroll
        for (int ki = 0; ki < 8; ki++) {
            int bi = ks * 8 + ki;
            int ch = (((bi * 4 + tg) ^ sw) << 2);
            uint4 h00 = *(const uint4*)&hsm[(g)      * 512 + ch];
            uint4 h01 = *(const uint4*)&hsm[(g + 8)  * 512 + ch];
            uint4 h10 = *(const uint4*)&hsm[(g + 16) * 512 + ch];
            uint4 h11 = *(const uint4*)&hsm[(g + 24) * 512 + ch];
            u32 p0h = prmt(h00.x, h00.y, 0x5410), p0l = prmt(h00.x, h00.y, 0x7632);
            u32 p2h = prmt(h00.z, h00.w, 0x5410), p2l = prmt(h00.z, h00.w, 0x7632);
            u32 p1h = prmt(h01.x, h01.y, 0x5410), p1l = prmt(h01.x, h01.y, 0x7632);
            u32 p3h = prmt(h01.z, h01.w, 0x5410), p3l = prmt(h01.z, h01.w, 0x7632);
            u32 q0h = prmt(h10.x, h10.y, 0x5410), q0l = prmt(h10.x, h10.y, 0x7632);
            u32 q2h = prmt(h10.z, h10.w, 0x5410), q2l = prmt(h10.z, h10.w, 0x7632);
            u32 q1h = prmt(h11.x, h11.y, 0x5410), q1l = prmt(h11.x, h11.y, 0x7632);
            u32 q3h = prmt(h11.z, h11.w, 0x5410), q3l = prmt(h11.z, h11.w, 0x7632);
            int wbase = ((g >> 1) * 32 + bi) * 8 + (g & 1) * 4 + tg;
#pragma unroll
            for (int ni = 0; ni < 8; ni++) {
                uint4 v = ws4[ni * 1024 + wbase];
                mma16816(D[0][ni], p0h, p1h, p2h, p3h, v.x, v.y);
                mma16816(D[0][ni], p0h, p1h, p2h, p3h, v.z, v.w);
                mma16816(D[0][ni], p0l, p1l, p2l, p3l, v.x, v.y);
                mma16816(D[1][ni], q0h, q1h, q2h, q3h, v.x, v.y);
                mma16816(D[1][ni], q0h, q1h, q2h, q3h, v.z, v.w);
                mma16816(D[1][ni], q0l, q1l, q2l, q3l, v.x, v.y);
            }
        }

        // ---- store partials ----
#pragma unroll
        for (int mt = 0; mt < 2; mt++)
#pragma unroll
            for (int ni = 0; ni < 8; ni++) {
                float* pp = &part[(ks * BPG + mt * 16 + g) * PSTRIDE + ni * 8 + tg * 2];
                float2 lo2 = {D[mt][ni][0], D[mt][ni][1]};
                float2 hi2 = {D[mt][ni][2], D[mt][ni][3]};
                *(float2*)pp = lo2;
                *(float2*)(pp + 8 * PSTRIDE) = hi2;
            }
        __syncthreads();

        // ---- combine: reduce over 4 k-warps, gates, flip-flop, write ----
        float* seqout = g_seq + ((size_t)(c * T_ + t)) * B_ * U_
                        + (size_t)(bg * BPG) * U_ + nc * UC + pu;
        u32* hout = g_hsplit + ((size_t)((t + 1) & 1) * C_ + c) * B_ * U_
                    + (size_t)(bg * BPG) * U_ + wcol;
#pragma unroll
        for (int r = 0; r < 8; r++) {
            int pb = pbq + r * 4;
            float sj = 0.f, sk = 0.f;
#pragma unroll
            for (int kq = 0; kq < 4; kq++) {
                const float* pr = &part[(kq * BPG + pb) * PSTRIDE];
                sj += pr[pu];
                sk += pr[pu + 32];
            }
            float zj = sj + xjr[r] + bj_r;
            float zk = sk + xkr[r] + bk_r;
            float jg = __fdividef(1.f, 1.f + __expf(-zj));
            float kg = __fdividef(1.f, 1.f + __expf(-zk));
            float h  = hprev[r];
            float hn = jg * (1.f - h) + (1.f - kg) * h;
            hprev[r] = hn;
            seqout[(size_t)pb * U_] = hn;
            __nv_bfloat16 nh, nl;
            split_bf(hn, nh, nl);
            hout[(size_t)pb * U_] =
                ((u32)__bfloat16_as_ushort(nl) << 16) | (u32)__bfloat16_as_ushort(nh);
        }

        if (t == T_ - 1) break;

        // ---- barrier arrive (release) ----
        __threadfence();
        __syncthreads();
        unsigned gen0 = 0;
        bool leader_done = false;
        if (tid == 0) {
            unsigned old;
            asm volatile("ld.acquire.gpu.u32 %0, [%1];"
                         : "=r"(gen0) : "l"(&g_bar_gen[dom]) : "memory");
            asm volatile("atom.acq_rel.gpu.add.u32 %0, [%1], 1;"
                         : "=r"(old) : "l"(&g_bar_count[dom]) : "memory");
            if (old == SC_DOM_BLKS - 1) {
                *(volatile unsigned*)&g_bar_count[dom] = 0;
                asm volatile("red.release.gpu.add.u32 [%0], 1;"
                             :: "l"(&g_bar_gen[dom]) : "memory");
                leader_done = true;
            }
        }

        // ---- prefetch x for t+1 while waiting ----
        {
            const float* xj = g_xproj
                + ((size_t)((c * 2 + 0) * T_ + t + 1)) * B_ * U_
                + (size_t)(bg * BPG) * U_ + nc * UC + pu;
            const float* xk = g_xproj
                + ((size_t)((c * 2 + 1) * T_ + t + 1)) * B_ * U_
                + (size_t)(bg * BPG) * U_ + nc * UC + pu;
#pragma unroll
            for (int r = 0; r < 8; r++) {
                xjr[r] = __ldcs(&xj[(size_t)(pbq + r * 4) * U_]);
                xkr[r] = __ldcs(&xk[(size_t)(pbq + r * 4) * U_]);
            }
        }

        // ---- barrier wait (acquire) ----
        if (tid == 0 && !leader_done) {
            unsigned gg;
            do {
                __nanosleep(20);
                asm volatile("ld.acquire.gpu.u32 %0, [%1];"
                             : "=r"(gg) : "l"(&g_bar_gen[dom]) : "memory");
            } while (gg == gen0);
        }
        __syncthreads();
    }
}

// ---------------------------------------------------------------------------
// Phase 3: oscillator unroll (unchanged)
// ---------------------------------------------------------------------------
__global__ __launch_bounds__(256) void osc_kernel(float* __restrict__ out)
{
    int n = blockIdx.x * 256 + threadIdx.x;
    int u  = n & (U_ - 1);
    int bt = n >> 9;
    int b  = bt & (B_ - 1);
    int t  = bt >> 6;

    size_t base = (size_t)t * B_ * U_ + (size_t)b * U_ + u;
    const size_t plane = (size_t)T_ * B_ * U_;
    float phi = g_seq[0 * plane + base];
    float om  = g_seq[1 * plane + base];
    float r   = g_seq[2 * plane + base];
    float mu  = g_seq[3 * plane + base];

    float* o = out + ((size_t)b * (T_ * OSC_) + (size_t)t * OSC_) * U_ + u;
    o[0] = r * __cosf(phi);
#pragma unroll
    for (int sstep = 1; sstep < OSC_; sstep++) {
        r   = r + (mu - r * r) * r;
        phi = phi + om;
        o[(size_t)sstep * U_] = r * __cosf(phi);
    }
}

// ---------------------------------------------------------------------------
// Launch
// ---------------------------------------------------------------------------
extern "C" void kernel_launch(void* const* d_in, const int* in_sizes, int n_in,
                              void* d_out, int out_size)
{
    const float* x   = (const float*)d_in[0];
    const float* h0  = (const float*)d_in[1];
    const float* Wjx = (const float*)d_in[2];
    const float* bjx = (const float*)d_in[3];
    const float* Wjh = (const float*)d_in[4];
    const float* bjh = (const float*)d_in[5];
    const float* Wkx = (const float*)d_in[6];
    const float* bkx = (const float*)d_in[7];
    const float* Wkh = (const float*)d_in[8];
    const float* bkh = (const float*)d_in[9];
    float* out = (float*)d_out;
    (void)in_sizes; (void)n_in; (void)out_size;

    cudaFuncSetAttribute(scan_kernel,
                         cudaFuncAttributeMaxDynamicSharedMemorySize,
                         SC_SMEM_BYTES);

    // Phase 1: projections. grid = (M/128, U/64, 8 planes)
    dim3 pg((B_ * T_) / 128, U_ / 64, 8);
    proj_mma_kernel<<<pg, 256>>>(x, Wjx, bjx, Wkx, bkx);

    // Phase 2: persistent scan — 128 CTAs x 128 threads, 8 software domains
    scan_kernel<<<C_ * NBG * NUC, SC_NTH, SC_SMEM_BYTES>>>(h0, Wjh, bjh, Wkh, bkh);

    // Phase 3: oscillator
    osc_kernel<<<(B_ * T_ * U_) / 256, 256>>>(out);
}

// round 16
// speedup vs baseline: 1.0572x; 1.0572x over previous
#include <cuda_runtime.h>
#include <cuda_bf16.h>
#include <cstdint>
#include <cstddef>

// Problem constants
#define C_ 4
#define B_ 64
#define T_ 512
#define D_ 256
#define U_ 512
#define OSC_ 5

typedef unsigned int u32;

// ---------------------------------------------------------------------------
// Helpers
// ---------------------------------------------------------------------------
__device__ __forceinline__ u32 prmt(u32 a, u32 b, u32 s) {
    u32 d;
    asm("prmt.b32 %0, %1, %2, %3;" : "=r"(d) : "r"(a), "r"(b), "r"(s));
    return d;
}

__device__ __forceinline__ u32 pack_bf(__nv_bfloat16 a, __nv_bfloat16 b) {
    return ((u32)__bfloat16_as_ushort(b) << 16) | (u32)__bfloat16_as_ushort(a);
}

__device__ __forceinline__ void split_bf(float v, __nv_bfloat16& hi, __nv_bfloat16& lo) {
    hi = __float2bfloat16(v);
    lo = __float2bfloat16(v - __bfloat162float(hi));
}

__device__ __forceinline__ void mma16816(float d[4], u32 a0, u32 a1, u32 a2, u32 a3,
                                         u32 b0, u32 b1) {
    asm("mma.sync.aligned.m16n8k16.row.col.f32.bf16.bf16.f32 "
        "{%0,%1,%2,%3}, {%4,%5,%6,%7}, {%8,%9}, {%0,%1,%2,%3};"
        : "+f"(d[0]), "+f"(d[1]), "+f"(d[2]), "+f"(d[3])
        : "r"(a0), "r"(a1), "r"(a2), "r"(a3), "r"(b0), "r"(b1));
}

__device__ __forceinline__ void ld4cg(u32& a, u32& b, u32& c, u32& d, const u32* p) {
    asm volatile("ld.global.cg.v4.u32 {%0,%1,%2,%3}, [%4];"
                 : "=r"(a), "=r"(b), "=r"(c), "=r"(d) : "l"(p));
}

// fragment permutation of h k-layout: within each 16-k block, thread tg's
// four k values {2tg, 2tg+1, 2tg+8, 2tg+9} become contiguous at [4tg..4tg+3]
__device__ __forceinline__ int permu(int u) {
    int r = u & 15;
    int t4 = (r & 7) >> 1;
    int slot = ((r >> 3) << 1) | (r & 1);
    return (u & ~15) | (t4 << 2) | slot;
}

// fast reciprocal on the FMA pipe: bit-trick seed + 2 Newton iterations
// (rel err ~6e-6; avoids the MUFU rcp which binds the combine phase)
__device__ __forceinline__ float fastrcp(float d) {
    float y = __uint_as_float(0x7EF311C3u - __float_as_uint(d));
    y = y * (2.0f - d * y);
    y = y * (2.0f - d * y);
    return y;
}

// ---------------------------------------------------------------------------
// Scratch (device globals — no allocation allowed)
// ---------------------------------------------------------------------------
__device__ float g_xproj[8ull * T_ * B_ * U_];
__device__ float g_seq[(size_t)C_ * T_ * B_ * U_];
// double-buffered packed h (k-permuted layout): low16 = bf16 hi, high16 = lo
__device__ u32 g_hsplit[2ull * C_ * B_ * U_];

// per-(cell,bgroup) barrier state: 8 domains of 16 blocks
__device__ unsigned g_bar_count[8] = {0};
__device__ unsigned g_bar_gen[8]   = {0};

// ---------------------------------------------------------------------------
// Phase 1: input projection GEMM via bf16 hi/lo split mma (verified R9-R14)
// ---------------------------------------------------------------------------
#define PJ_XPAD 40
#define PJ_WPAD 40

__global__ __launch_bounds__(256) void proj_mma_kernel(
    const float* __restrict__ x,
    const float* __restrict__ Wjx, const float* __restrict__ bjx,
    const float* __restrict__ Wkx, const float* __restrict__ bkx)
{
    __shared__ __nv_bfloat16 xs_hi[128 * PJ_XPAD];
    __shared__ __nv_bfloat16 xs_lo[128 * PJ_XPAD];
    __shared__ __nv_bfloat16 ws_hi[64 * PJ_WPAD];
    __shared__ __nv_bfloat16 ws_lo[64 * PJ_WPAD];

    const int zi = blockIdx.z;
    const int c  = zi >> 1;
    const int gt = zi & 1;
    const float* W  = (gt ? Wkx : Wjx) + (size_t)c * D_ * U_;
    const float* bi = (gt ? bkx : bjx) + (size_t)c * U_;

    const int m0 = blockIdx.x * 128;
    const int n0 = blockIdx.y * 64;
    const int tid = threadIdx.x;
    const int w   = tid >> 5;
    const int l   = tid & 31;
    const int g   = l >> 2;
    const int tg  = l & 3;
    const int wm  = w & 1;
    const int wn  = w >> 1;

    float2 bias2[2];
#pragma unroll
    for (int ni = 0; ni < 2; ni++)
        bias2[ni] = *(const float2*)&bi[n0 + wn * 16 + ni * 8 + tg * 2];

    float D[4][2][4];
#pragma unroll
    for (int mi = 0; mi < 4; mi++)
#pragma unroll
        for (int ni = 0; ni < 2; ni++)
#pragma unroll
            for (int q = 0; q < 4; q++) D[mi][ni][q] = 0.f;

    const int xr   = tid >> 1;
    const int half = tid & 1;
    const int wkr  = tid >> 3;
    const int wnc  = (tid & 7) * 8;

    for (int kc = 0; kc < 8; kc++) {
        __syncthreads();
        const float* xp = &x[(size_t)(m0 + xr) * D_ + kc * 32 + half * 16];
#pragma unroll
        for (int q = 0; q < 4; q++) {
            float4 v = *(const float4*)&xp[q * 4];
            __nv_bfloat16 h0, l0, h1, l1, h2, l2, h3, l3;
            split_bf(v.x, h0, l0); split_bf(v.y, h1, l1);
            split_bf(v.z, h2, l2); split_bf(v.w, h3, l3);
            int e = xr * PJ_XPAD + half * 16 + q * 4;
            *(u32*)&xs_hi[e]     = pack_bf(h0, h1);
            *(u32*)&xs_hi[e + 2] = pack_bf(h2, h3);
            *(u32*)&xs_lo[e]     = pack_bf(l0, l1);
            *(u32*)&xs_lo[e + 2] = pack_bf(l2, l3);
        }
        const float* wp = &W[(size_t)(kc * 32 + wkr) * U_ + n0 + wnc];
        float4 w0 = *(const float4*)wp;
        float4 w1 = *(const float4*)(wp + 4);
        float wv[8] = {w0.x, w0.y, w0.z, w0.w, w1.x, w1.y, w1.z, w1.w};
#pragma unroll
        for (int j = 0; j < 8; j++) {
            __nv_bfloat16 hh, ll;
            split_bf(wv[j], hh, ll);
            ws_hi[(wnc + j) * PJ_WPAD + wkr] = hh;
            ws_lo[(wnc + j) * PJ_WPAD + wkr] = ll;
        }
        __syncthreads();

        u32 Bh[2][2][2], Bl[2][2][2];
#pragma unroll
        for (int ni = 0; ni < 2; ni++)
#pragma unroll
            for (int ki = 0; ki < 2; ki++) {
                int e = (wn * 16 + ni * 8 + g) * PJ_WPAD + ki * 16 + tg * 2;
                Bh[ni][ki][0] = *(const u32*)&ws_hi[e];
                Bh[ni][ki][1] = *(const u32*)&ws_hi[e + 8];
                Bl[ni][ki][0] = *(const u32*)&ws_lo[e];
                Bl[ni][ki][1] = *(const u32*)&ws_lo[e + 8];
            }

#pragma unroll
        for (int mi = 0; mi < 4; mi++)
#pragma unroll
            for (int ki = 0; ki < 2; ki++) {
                int rb = (wm * 64 + mi * 16 + g) * PJ_XPAD + ki * 16 + tg * 2;
                u32 ah0 = *(const u32*)&xs_hi[rb];
                u32 ah1 = *(const u32*)&xs_hi[rb + 8 * PJ_XPAD];
                u32 ah2 = *(const u32*)&xs_hi[rb + 8];
                u32 ah3 = *(const u32*)&xs_hi[rb + 8 * PJ_XPAD + 8];
                u32 al0 = *(const u32*)&xs_lo[rb];
                u32 al1 = *(const u32*)&xs_lo[rb + 8 * PJ_XPAD];
                u32 al2 = *(const u32*)&xs_lo[rb + 8];
                u32 al3 = *(const u32*)&xs_lo[rb + 8 * PJ_XPAD + 8];
#pragma unroll
                for (int ni = 0; ni < 2; ni++) {
                    mma16816(D[mi][ni], ah0, ah1, ah2, ah3, Bh[ni][ki][0], Bh[ni][ki][1]);
                    mma16816(D[mi][ni], ah0, ah1, ah2, ah3, Bl[ni][ki][0], Bl[ni][ki][1]);
                    mma16816(D[mi][ni], al0, al1, al2, al3, Bh[ni][ki][0], Bh[ni][ki][1]);
                }
            }
    }

#pragma unroll
    for (int mi = 0; mi < 4; mi++)
#pragma unroll
        for (int ni = 0; ni < 2; ni++) {
            int col = n0 + wn * 16 + ni * 8 + tg * 2;
#pragma unroll
            for (int h = 0; h < 2; h++) {
                int m  = m0 + wm * 64 + mi * 16 + g + h * 8;
                int bb = m >> 9;
                int tt = m & 511;
                size_t off = ((size_t)(zi * T_ + tt) * B_ + bb) * U_ + col;
                float2 o;
                o.x = D[mi][ni][2 * h + 0] + bias2[ni].x;
                o.y = D[mi][ni][2 * h + 1] + bias2[ni].y;
                *(float2*)&g_xproj[off] = o;
            }
        }
}

// ---------------------------------------------------------------------------
// Phase 2: persistent scan — 128 plain CTAs (1/SM), software barrier in
//   8 domains of 16 (cell x bgroup). Warp = (m-half, k-quarter); h in
//   k-permuted packed layout -> one ld.cg.v4 per row per 16-k block.
//   Combine uses fused single-division flip-flop update + FMA-pipe rcp.
// ---------------------------------------------------------------------------
#define NBG  2
#define BPG  32
#define NUC  16
#define UC   32
#define KST  260                         // uint2 per col (256 + pad)
#define W_SMEM_U2 (64 * KST)             // 133120 B
#define PSTRIDE 66
#define PART_FLOATS (4 * BPG * PSTRIDE)  // 8448 floats = 33792 B
#define SC_SMEM_BYTES (W_SMEM_U2 * 8 + PART_FLOATS * 4)   // 166912 B
#define SC_DOM_BLKS 16

__global__ __launch_bounds__(256, 1) void scan_kernel(
    const float* __restrict__ h0,
    const float* __restrict__ Wjh, const float* __restrict__ bjh,
    const float* __restrict__ Wkh, const float* __restrict__ bkh)
{
    extern __shared__ char smraw[];
    uint2* ws   = (uint2*)smraw;                     // [64 cols][KST]
    float* part = (float*)(smraw + W_SMEM_U2 * 8);   // [4 ks][BPG][PSTRIDE]

    const int blk = blockIdx.x;          // c*32 + bg*16 + nc
    const int c   = blk >> 5;
    const int bg  = (blk >> 4) & 1;
    const int nc  = blk & 15;
    const int dom = c * 2 + bg;
    const int tid = threadIdx.x;
    const int w   = tid >> 5;
    const int l   = tid & 31;
    const int ms  = w >> 2;              // m-half: batches ms*16..+16
    const int ks  = w & 3;               // k-quarter: 128 k
    const int g   = l >> 2;
    const int tg  = l & 3;
    const int pu  = tid & 31;            // combine: u offset
    const int pbq = tid >> 5;            // combine: base batch (0..7)

    // ---- one-time: weights -> smem (hi|lo packed pairs along k) ----
    for (int idx = tid; idx < 64 * 256; idx += 256) {
        int col  = idx >> 8;             // 0..63 = gate*32 + uu
        int kk   = idx & 255;
        int gate = col >> 5;
        int uu   = col & 31;
        const float* Wc = (gate ? Wkh : Wjh) + (size_t)c * U_ * U_;
        int ucol = nc * UC + uu;
        float w0 = Wc[(size_t)(2 * kk + 0) * U_ + ucol];
        float w1 = Wc[(size_t)(2 * kk + 1) * U_ + ucol];
        __nv_bfloat16 h0b, l0b, h1b, l1b;
        split_bf(w0, h0b, l0b);
        split_bf(w1, h1b, l1b);
        ws[col * KST + kk] = make_uint2(pack_bf(h0b, h1b), pack_bf(l0b, l1b));
    }

    const float bj_r = bjh[c * U_ + nc * UC + pu];
    const float bk_r = bkh[c * U_ + nc * UC + pu];
    const int  pcol  = permu(nc * UC + pu);          // permuted h column

    // ---- pack h0 slice into buffer 0 (permuted cols); h_prev in regs ----
    float hprev[4];
    {
        u32* buf0 = g_hsplit + (size_t)c * B_ * U_;
#pragma unroll
        for (int r = 0; r < 4; r++) {
            int b = bg * BPG + pbq + r * 8;
            float hv = h0[(size_t)c * B_ * U_ + (size_t)b * U_ + nc * UC + pu];
            hprev[r] = hv;
            __nv_bfloat16 nh, nl;
            split_bf(hv, nh, nl);
            buf0[(size_t)b * U_ + pcol] =
                ((u32)__bfloat16_as_ushort(nl) << 16) | (u32)__bfloat16_as_ushort(nh);
        }
    }

    // ---- prefetch x projections for t = 0 ----
    float xjr[4], xkr[4];
    {
        const float* xj = g_xproj + ((size_t)(c * 2 + 0) * T_) * B_ * U_
                          + (size_t)(bg * BPG) * U_ + nc * UC + pu;
        const float* xk = g_xproj + ((size_t)(c * 2 + 1) * T_) * B_ * U_
                          + (size_t)(bg * BPG) * U_ + nc * UC + pu;
#pragma unroll
        for (int r = 0; r < 4; r++) {
            xjr[r] = __ldcs(&xj[(size_t)(pbq + r * 8) * U_]);
            xkr[r] = __ldcs(&xk[(size_t)(pbq + r * 8) * U_]);
        }
    }

    // ---- pre-loop domain barrier (publish h0 pack + smem weights) ----
    __threadfence();
    __syncthreads();
    if (tid == 0) {
        unsigned gen0, old;
        asm volatile("ld.acquire.gpu.u32 %0, [%1];"
                     : "=r"(gen0) : "l"(&g_bar_gen[dom]) : "memory");
        asm volatile("atom.acq_rel.gpu.add.u32 %0, [%1], 1;"
                     : "=r"(old) : "l"(&g_bar_count[dom]) : "memory");
        if (old == SC_DOM_BLKS - 1) {
            *(volatile unsigned*)&g_bar_count[dom] = 0;
            asm volatile("red.release.gpu.add.u32 [%0], 1;"
                         :: "l"(&g_bar_gen[dom]) : "memory");
        } else {
            unsigned gg;
            do {
                __nanosleep(20);
                asm volatile("ld.acquire.gpu.u32 %0, [%1];"
                             : "=r"(gg) : "l"(&g_bar_gen[dom]) : "memory");
            } while (gg == gen0);
        }
    }
    __syncthreads();

    u32 raw[8][8];

    for (int t = 0; t < T_; t++) {
        const u32* hrow = g_hsplit
            + ((size_t)(t & 1) * C_ + c) * B_ * U_
            + (size_t)(bg * BPG + ms * 16) * U_;
        const u32* rg = hrow + (size_t)g * U_;
        const u32* rh = hrow + (size_t)(g + 8) * U_;

        // ---- 16 LDG.128 per thread, all in flight ----
#pragma unroll
        for (int ki = 0; ki < 8; ki++) {
            int idx = ks * 128 + ki * 16 + tg * 4;
            ld4cg(raw[ki][0], raw[ki][1], raw[ki][2], raw[ki][3], rg + idx);
            ld4cg(raw[ki][4], raw[ki][5], raw[ki][6], raw[ki][7], rh + idx);
        }

        float D[8][4];
#pragma unroll
        for (int ni = 0; ni < 8; ni++)
#pragma unroll
            for (int q = 0; q < 4; q++) D[ni][q] = 0.f;

#pragma unroll
        for (int ki = 0; ki < 8; ki++) {
            const u32* r0 = raw[ki];
            u32 a0h = prmt(r0[0], r0[1], 0x5410), a0l = prmt(r0[0], r0[1], 0x7632);
            u32 a2h = prmt(r0[2], r0[3], 0x5410), a2l = prmt(r0[2], r0[3], 0x7632);
            u32 a1h = prmt(r0[4], r0[5], 0x5410), a1l = prmt(r0[4], r0[5], 0x7632);
            u32 a3h = prmt(r0[6], r0[7], 0x5410), a3l = prmt(r0[6], r0[7], 0x7632);
            int kkb = ks * 64 + ki * 8 + tg;
#pragma unroll
            for (int ni = 0; ni < 8; ni++) {
                uint2 v0 = ws[(ni * 8 + g) * KST + kkb];
                uint2 v1 = ws[(ni * 8 + g) * KST + kkb + 4];
                mma16816(D[ni], a0h, a1h, a2h, a3h, v0.x, v1.x);
                mma16816(D[ni], a0h, a1h, a2h, a3h, v0.y, v1.y);
                mma16816(D[ni], a0l, a1l, a2l, a3l, v0.x, v1.x);
            }
        }

        // ---- store partials ----
        {
            int prow = ks * BPG + ms * 16 + g;
#pragma unroll
            for (int ni = 0; ni < 8; ni++) {
                float* pp = &part[prow * PSTRIDE + ni * 8 + tg * 2];
                float2 lo2 = {D[ni][0], D[ni][1]};
                float2 hi2 = {D[ni][2], D[ni][3]};
                *(float2*)pp = lo2;
                *(float2*)(pp + 8 * PSTRIDE) = hi2;
            }
        }
        __syncthreads();

        // ---- combine: reduce over 4 k-warps, fused flip-flop update ----
        // h' = [(1-h)(1+b) + h*b*(1+a)] / [(1+a)(1+b)],  a=e^{-zj}, b=e^{-zk}
        // (one reciprocal instead of two sigmoid divides; rcp on FMA pipe)
        float* seqout = g_seq + ((size_t)(c * T_ + t)) * B_ * U_
                        + (size_t)(bg * BPG) * U_ + nc * UC + pu;
        u32* hout = g_hsplit + ((size_t)((t + 1) & 1) * C_ + c) * B_ * U_
                    + (size_t)(bg * BPG) * U_ + pcol;
#pragma unroll
        for (int r = 0; r < 4; r++) {
            int pb = pbq + r * 8;
            float sj = 0.f, sk = 0.f;
#pragma unroll
            for (int kq = 0; kq < 4; kq++) {
                const float* pr = &part[(kq * BPG + pb) * PSTRIDE];
                sj += pr[pu];
                sk += pr[pu + 32];
            }
            float zj = sj + xjr[r] + bj_r;
            float zk = sk + xkr[r] + bk_r;
            float a = __expf(-zj);
            float b = __expf(-zk);
            float pa = 1.f + a;
            float pb2 = 1.f + b;
            float h  = hprev[r];
            float numer = (1.f - h) * pb2 + h * b * pa;
            float hn = numer * fastrcp(pa * pb2);
            hprev[r] = hn;
            seqout[(size_t)pb * U_] = hn;
            __nv_bfloat16 nh, nl;
            split_bf(hn, nh, nl);
            hout[(size_t)pb * U_] =
                ((u32)__bfloat16_as_ushort(nl) << 16) | (u32)__bfloat16_as_ushort(nh);
        }

        if (t == T_ - 1) break;

        // ---- barrier arrive (release) ----
        __threadfence();
        __syncthreads();
        unsigned gen0 = 0;
        bool leader_done = false;
        if (tid == 0) {
            unsigned old;
            asm volatile("ld.acquire.gpu.u32 %0, [%1];"
                         : "=r"(gen0) : "l"(&g_bar_gen[dom]) : "memory");
            asm volatile("atom.acq_rel.gpu.add.u32 %0, [%1], 1;"
                         : "=r"(old) : "l"(&g_bar_count[dom]) : "memory");
            if (old == SC_DOM_BLKS - 1) {
                *(volatile unsigned*)&g_bar_count[dom] = 0;
                asm volatile("red.release.gpu.add.u32 [%0], 1;"
                             :: "l"(&g_bar_gen[dom]) : "memory");
                leader_done = true;
            }
        }

        // ---- prefetch x for t+1 while waiting ----
        {
            const float* xj = g_xproj
                + ((size_t)((c * 2 + 0) * T_ + t + 1)) * B_ * U_
                + (size_t)(bg * BPG) * U_ + nc * UC + pu;
            const float* xk = g_xproj
                + ((size_t)((c * 2 + 1) * T_ + t + 1)) * B_ * U_
                + (size_t)(bg * BPG) * U_ + nc * UC + pu;
#pragma unroll
            for (int r = 0; r < 4; r++) {
                xjr[r] = __ldcs(&xj[(size_t)(pbq + r * 8) * U_]);
                xkr[r] = __ldcs(&xk[(size_t)(pbq + r * 8) * U_]);
            }
        }

        // ---- barrier wait (acquire) ----
        if (tid == 0 && !leader_done) {
            unsigned gg;
            do {
                __nanosleep(20);
                asm volatile("ld.acquire.gpu.u32 %0, [%1];"
                             : "=r"(gg) : "l"(&g_bar_gen[dom]) : "memory");
            } while (gg == gen0);
        }
        __syncthreads();
    }
}

// ---------------------------------------------------------------------------
// Phase 3: oscillator unroll (unchanged)
// ---------------------------------------------------------------------------
__global__ __launch_bounds__(256) void osc_kernel(float* __restrict__ out)
{
    int n = blockIdx.x * 256 + threadIdx.x;
    int u  = n & (U_ - 1);
    int bt = n >> 9;
    int b  = bt & (B_ - 1);
    int t  = bt >> 6;

    size_t base = (size_t)t * B_ * U_ + (size_t)b * U_ + u;
    const size_t plane = (size_t)T_ * B_ * U_;
    float phi = g_seq[0 * plane + base];
    float om  = g_seq[1 * plane + base];
    float r   = g_seq[2 * plane + base];
    float mu  = g_seq[3 * plane + base];

    float* o = out + ((size_t)b * (T_ * OSC_) + (size_t)t * OSC_) * U_ + u;
    o[0] = r * __cosf(phi);
#pragma unroll
    for (int sstep = 1; sstep < OSC_; sstep++) {
        r   = r + (mu - r * r) * r;
        phi = phi + om;
        o[(size_t)sstep * U_] = r * __cosf(phi);
    }
}

// ---------------------------------------------------------------------------
// Launch
// ---------------------------------------------------------------------------
extern "C" void kernel_launch(void* const* d_in, const int* in_sizes, int n_in,
                              void* d_out, int out_size)
{
    const float* x   = (const float*)d_in[0];
    const float* h0  = (const float*)d_in[1];
    const float* Wjx = (const float*)d_in[2];
    const float* bjx = (const float*)d_in[3];
    const float* Wjh = (const float*)d_in[4];
    const float* bjh = (const float*)d_in[5];
    const float* Wkx = (const float*)d_in[6];
    const float* bkx = (const float*)d_in[7];
    const float* Wkh = (const float*)d_in[8];
    const float* bkh = (const float*)d_in[9];
    float* out = (float*)d_out;
    (void)in_sizes; (void)n_in; (void)out_size;

    cudaFuncSetAttribute(scan_kernel,
                         cudaFuncAttributeMaxDynamicSharedMemorySize,
                         SC_SMEM_BYTES);

    // Phase 1: projections. grid = (M/128, U/64, 8 planes)
    dim3 pg((B_ * T_) / 128, U_ / 64, 8);
    proj_mma_kernel<<<pg, 256>>>(x, Wjx, bjx, Wkx, bkx);

    // Phase 2: persistent scan — 128 plain CTAs, 8 software sync domains
    scan_kernel<<<C_ * NBG * NUC, 256, SC_SMEM_BYTES>>>(h0, Wjh, bjh, Wkh, bkh);

    // Phase 3: oscillator
    osc_kernel<<<(B_ * T_ * U_) / 256, 256>>>(out);
}